// round 1
// baseline (speedup 1.0000x reference)
#include <cuda_runtime.h>

// Problem constants (fixed-shape problem)
constexpr int Bc = 2, Hc = 12, Sc = 2048, Dc = 64, Gc = 128;
constexpr int KC = Sc / 128;   // 16 key chunks for the global-query full-attention pass
constexpr int QT = 128;        // query tile
constexpr long CTX_ELEMS = (long)Bc * Hc * Sc * Dc;

// Scratch (static __device__ arrays: allocation-free)
__device__ int   d_gidx[Bc * Gc];
__device__ int   d_gcnt[Bc];
__device__ float d_pacc[(size_t)Bc * Hc * KC * Gc * Dc];  // partial ctx accumulators
__device__ float d_pm[Bc * Hc * KC * Gc];                 // partial row max
__device__ float d_pl[Bc * Hc * KC * Gc];                 // partial row sum

// Shared memory layout (floats):
//   phase 1: qsT [64][128] at 0, ksT [64][128] at 8192
//   phase 2: probsS [128][129] at 0 (overlays qsT/ksT)
//   gvs [128][64] at 16512, red [128][16] at 24704
constexpr int SM_FLOATS = 16512 + 8192 + 2048;   // 26752 floats = 107008 bytes
constexpr int SMEM_BYTES = SM_FLOATS * 4;

#define NEG_INF __int_as_float(0xff800000)

// ---------------------------------------------------------------------------
// Kernel A: stable-order global index list per batch
// ---------------------------------------------------------------------------
__global__ void build_index_kernel(const int* __restrict__ mask) {
    int b = blockIdx.x;
    __shared__ int cnt[256];
    __shared__ int off[256];
    int tid = threadIdx.x;
    const int SEG = Sc / 256;  // 8
    int base = tid * SEG;
    int c = 0;
#pragma unroll
    for (int i = 0; i < SEG; i++) c += (mask[b * Sc + base + i] > 0);
    cnt[tid] = c;
    __syncthreads();
    if (tid == 0) {
        int s = 0;
        for (int t = 0; t < 256; t++) { off[t] = s; s += cnt[t]; }
        d_gcnt[b] = (s < Gc) ? s : Gc;
    }
    __syncthreads();
    int o = off[tid];
#pragma unroll
    for (int i = 0; i < SEG; i++) {
        if (mask[b * Sc + base + i] > 0) {
            if (o < Gc) d_gidx[b * Gc + o] = base + i;
            o++;
        }
    }
}

// ---------------------------------------------------------------------------
// Kernel B: global-branch attention for ALL queries + probs output (with
// fused zero-fill of the probs tail) + context output.
// Grid: (S/QT, H, B), 256 threads.
// ---------------------------------------------------------------------------
__global__ void __launch_bounds__(256, 2) global_attn_kernel(
    const float* __restrict__ q, const float* __restrict__ k,
    const float* __restrict__ v, float* __restrict__ ctx,
    float* __restrict__ probs) {
    extern __shared__ float sm[];
    float* qsT    = sm;            // [64][128]
    float* ksT    = sm + 8192;     // [64][128]
    float* probsS = sm;            // [128][129] (overlays qsT/ksT after GEMM1)
    float* gvs    = sm + 16512;    // [128][64]
    float* red    = sm + 24704;    // [128][16]

    int tid = threadIdx.x;
    int h = blockIdx.y, b = blockIdx.z;
    int bh = b * Hc + h;
    int q0 = blockIdx.x * QT;
    int c = d_gcnt[b];

    const float* qb = q + (size_t)bh * Sc * Dc;
    const float* kb = k + (size_t)bh * Sc * Dc;
    const float* vb = v + (size_t)bh * Sc * Dc;

    // ---- Load q tile (transposed), gathered global K (transposed), global V
    {
        int r = tid & 127, half = tid >> 7;
        int d0base = half * 32;
        const float* qrow = qb + (size_t)(q0 + r) * Dc;
#pragma unroll
        for (int d0 = 0; d0 < 32; d0 += 4) {
            int dd = d0base + d0;
            float4 t = *(const float4*)(qrow + dd);
            qsT[(dd + 0) * 128 + r] = t.x;
            qsT[(dd + 1) * 128 + r] = t.y;
            qsT[(dd + 2) * 128 + r] = t.z;
            qsT[(dd + 3) * 128 + r] = t.w;
        }
        if (r < c) {
            int gi = d_gidx[b * Gc + r];
            const float* krow = kb + (size_t)gi * Dc;
            const float* vrow = vb + (size_t)gi * Dc;
#pragma unroll
            for (int d0 = 0; d0 < 32; d0 += 4) {
                int dd = d0base + d0;
                float4 t = *(const float4*)(krow + dd);
                ksT[(dd + 0) * 128 + r] = t.x;
                ksT[(dd + 1) * 128 + r] = t.y;
                ksT[(dd + 2) * 128 + r] = t.z;
                ksT[(dd + 3) * 128 + r] = t.w;
                *(float4*)(gvs + r * 64 + dd) = *(const float4*)(vrow + dd);
            }
        } else {
#pragma unroll
            for (int d0 = 0; d0 < 32; d0 += 4) {
                int dd = d0base + d0;
                ksT[(dd + 0) * 128 + r] = 0.f;
                ksT[(dd + 1) * 128 + r] = 0.f;
                ksT[(dd + 2) * 128 + r] = 0.f;
                ksT[(dd + 3) * 128 + r] = 0.f;
                *(float4*)(gvs + r * 64 + dd) = make_float4(0.f, 0.f, 0.f, 0.f);
            }
        }
    }
    __syncthreads();

    // ---- GEMM1: scores[128q][128k], 8x8 per thread, warp = 8x4 thread tiles
    int lane = tid & 31, w = tid >> 5;
    int tx = ((w & 1) << 3) + (lane & 7);   // 0..15 key group
    int ty = ((w >> 1) << 2) + (lane >> 3); // 0..15 query group
    int tx8 = tx * 8, ty8 = ty * 8;

    float acc[8][8];
#pragma unroll
    for (int i = 0; i < 8; i++)
#pragma unroll
        for (int jj = 0; jj < 8; jj++) acc[i][jj] = 0.f;

#pragma unroll 4
    for (int d = 0; d < 64; d++) {
        float a[8], bb[8];
        *(float4*)(a)      = *(const float4*)(qsT + d * 128 + ty8);
        *(float4*)(a + 4)  = *(const float4*)(qsT + d * 128 + ty8 + 4);
        *(float4*)(bb)     = *(const float4*)(ksT + d * 128 + tx8);
        *(float4*)(bb + 4) = *(const float4*)(ksT + d * 128 + tx8 + 4);
#pragma unroll
        for (int i = 0; i < 8; i++)
#pragma unroll
            for (int jj = 0; jj < 8; jj++)
                acc[i][jj] = fmaf(a[i], bb[jj], acc[i][jj]);
    }

    // scale + invalid-key mask
#pragma unroll
    for (int jj = 0; jj < 8; jj++) {
        bool inval = (tx8 + jj) >= c;
#pragma unroll
        for (int i = 0; i < 8; i++)
            acc[i][jj] = inval ? NEG_INF : acc[i][jj] * 0.125f;
    }

    // ---- softmax (row reductions via smem)
    float m[8], l[8];
#pragma unroll
    for (int i = 0; i < 8; i++) {
        float rm = acc[i][0];
#pragma unroll
        for (int jj = 1; jj < 8; jj++) rm = fmaxf(rm, acc[i][jj]);
        red[(ty8 + i) * 16 + tx] = rm;
    }
    __syncthreads();
#pragma unroll
    for (int i = 0; i < 8; i++) {
        const float* rr = red + (ty8 + i) * 16;
        float rm = rr[0];
#pragma unroll
        for (int t = 1; t < 16; t++) rm = fmaxf(rm, rr[t]);
        m[i] = rm;
    }
    __syncthreads();
#pragma unroll
    for (int i = 0; i < 8; i++) {
        float rs = 0.f;
#pragma unroll
        for (int jj = 0; jj < 8; jj++) {
            float e = __expf(acc[i][jj] - m[i]);
            acc[i][jj] = e;
            rs += e;
        }
        red[(ty8 + i) * 16 + tx] = rs;
    }
    __syncthreads();
#pragma unroll
    for (int i = 0; i < 8; i++) {
        const float* rr = red + (ty8 + i) * 16;
        float rs = 0.f;
#pragma unroll
        for (int t = 0; t < 16; t++) rs += rr[t];
        l[i] = rs;
    }
    // normalized probs into smem (overlays qsT/ksT; all reads of those done)
#pragma unroll
    for (int i = 0; i < 8; i++) {
        float inv = 1.0f / l[i];
#pragma unroll
        for (int jj = 0; jj < 8; jj++)
            probsS[(ty8 + i) * 129 + tx8 + jj] = acc[i][jj] * inv;
    }
    __syncthreads();

    // ---- probs gmem write: 128 computed cols + 1920 zeros per row, float4
    {
        float* prow = probs + ((size_t)bh * Sc + q0) * Sc;
        for (int i2 = tid; i2 < 128 * 512; i2 += 256) {
            int rr = i2 >> 9, c4 = i2 & 511;
            float4 val = make_float4(0.f, 0.f, 0.f, 0.f);
            if (c4 < 32) {
                const float* p = probsS + rr * 129 + c4 * 4;
                val = make_float4(p[0], p[1], p[2], p[3]);
            }
            *(float4*)(prow + (size_t)rr * Sc + (c4 << 2)) = val;
        }
    }

    // ---- GEMM2: ctx[128q][64d] = probs @ gv. thread: 1 row x 32 d-cols.
    {
        int r2 = tid >> 1, dg = tid & 1;
        float4 a4[8];
#pragma unroll
        for (int t = 0; t < 8; t++) a4[t] = make_float4(0.f, 0.f, 0.f, 0.f);
#pragma unroll 4
        for (int j = 0; j < 128; j++) {
            float p = probsS[r2 * 129 + j];
            const float4* g4 = (const float4*)(gvs + j * 64 + dg * 32);
#pragma unroll
            for (int t = 0; t < 8; t++) {
                float4 g = g4[t];
                a4[t].x = fmaf(p, g.x, a4[t].x);
                a4[t].y = fmaf(p, g.y, a4[t].y);
                a4[t].z = fmaf(p, g.z, a4[t].z);
                a4[t].w = fmaf(p, g.w, a4[t].w);
            }
        }
        float* crow = ctx + ((size_t)bh * Sc + q0 + r2) * Dc + dg * 32;
#pragma unroll
        for (int t = 0; t < 8; t++) ((float4*)crow)[t] = a4[t];
    }
}

// ---------------------------------------------------------------------------
// Kernel C: full attention for the global QUERIES, split-KV flash partials.
// Grid: (KC, H, B). Each block: 128 global-query rows x 128-key chunk.
// ---------------------------------------------------------------------------
__global__ void __launch_bounds__(256, 2) global_query_full_kernel(
    const float* __restrict__ q, const float* __restrict__ k,
    const float* __restrict__ v) {
    extern __shared__ float sm[];
    float* qsT    = sm;
    float* ksT    = sm + 8192;
    float* probsS = sm;
    float* gvs    = sm + 16512;
    float* red    = sm + 24704;

    int tid = threadIdx.x;
    int kc = blockIdx.x;
    int h = blockIdx.y, b = blockIdx.z;
    int bh = b * Hc + h;
    int k0 = kc * 128;
    int c = d_gcnt[b];

    const float* qb = q + (size_t)bh * Sc * Dc;
    const float* kb = k + (size_t)bh * Sc * Dc;
    const float* vb = v + (size_t)bh * Sc * Dc;

    // ---- Load: q rows are gathered global queries; keys/values are chunk rows
    {
        int r = tid & 127, half = tid >> 7;
        int d0base = half * 32;
        if (r < c) {
            int gi = d_gidx[b * Gc + r];
            const float* qrow = qb + (size_t)gi * Dc;
#pragma unroll
            for (int d0 = 0; d0 < 32; d0 += 4) {
                int dd = d0base + d0;
                float4 t = *(const float4*)(qrow + dd);
                qsT[(dd + 0) * 128 + r] = t.x;
                qsT[(dd + 1) * 128 + r] = t.y;
                qsT[(dd + 2) * 128 + r] = t.z;
                qsT[(dd + 3) * 128 + r] = t.w;
            }
        } else {
#pragma unroll
            for (int d0 = 0; d0 < 32; d0 += 4) {
                int dd = d0base + d0;
                qsT[(dd + 0) * 128 + r] = 0.f;
                qsT[(dd + 1) * 128 + r] = 0.f;
                qsT[(dd + 2) * 128 + r] = 0.f;
                qsT[(dd + 3) * 128 + r] = 0.f;
            }
        }
        const float* krow = kb + (size_t)(k0 + r) * Dc;
        const float* vrow = vb + (size_t)(k0 + r) * Dc;
#pragma unroll
        for (int d0 = 0; d0 < 32; d0 += 4) {
            int dd = d0base + d0;
            float4 t = *(const float4*)(krow + dd);
            ksT[(dd + 0) * 128 + r] = t.x;
            ksT[(dd + 1) * 128 + r] = t.y;
            ksT[(dd + 2) * 128 + r] = t.z;
            ksT[(dd + 3) * 128 + r] = t.w;
            *(float4*)(gvs + r * 64 + dd) = *(const float4*)(vrow + dd);
        }
    }
    __syncthreads();

    int lane = tid & 31, w = tid >> 5;
    int tx = ((w & 1) << 3) + (lane & 7);
    int ty = ((w >> 1) << 2) + (lane >> 3);
    int tx8 = tx * 8, ty8 = ty * 8;

    float acc[8][8];
#pragma unroll
    for (int i = 0; i < 8; i++)
#pragma unroll
        for (int jj = 0; jj < 8; jj++) acc[i][jj] = 0.f;

#pragma unroll 4
    for (int d = 0; d < 64; d++) {
        float a[8], bb[8];
        *(float4*)(a)      = *(const float4*)(qsT + d * 128 + ty8);
        *(float4*)(a + 4)  = *(const float4*)(qsT + d * 128 + ty8 + 4);
        *(float4*)(bb)     = *(const float4*)(ksT + d * 128 + tx8);
        *(float4*)(bb + 4) = *(const float4*)(ksT + d * 128 + tx8 + 4);
#pragma unroll
        for (int i = 0; i < 8; i++)
#pragma unroll
            for (int jj = 0; jj < 8; jj++)
                acc[i][jj] = fmaf(a[i], bb[jj], acc[i][jj]);
    }
#pragma unroll
    for (int i = 0; i < 8; i++)
#pragma unroll
        for (int jj = 0; jj < 8; jj++) acc[i][jj] *= 0.125f;

    // partial softmax stats (all 128 keys in chunk are valid)
    float m[8], l[8];
#pragma unroll
    for (int i = 0; i < 8; i++) {
        float rm = acc[i][0];
#pragma unroll
        for (int jj = 1; jj < 8; jj++) rm = fmaxf(rm, acc[i][jj]);
        red[(ty8 + i) * 16 + tx] = rm;
    }
    __syncthreads();
#pragma unroll
    for (int i = 0; i < 8; i++) {
        const float* rr = red + (ty8 + i) * 16;
        float rm = rr[0];
#pragma unroll
        for (int t = 1; t < 16; t++) rm = fmaxf(rm, rr[t]);
        m[i] = rm;
    }
    __syncthreads();
#pragma unroll
    for (int i = 0; i < 8; i++) {
        float rs = 0.f;
#pragma unroll
        for (int jj = 0; jj < 8; jj++) {
            float e = __expf(acc[i][jj] - m[i]);
            acc[i][jj] = e;
            rs += e;
        }
        red[(ty8 + i) * 16 + tx] = rs;
    }
    __syncthreads();
#pragma unroll
    for (int i = 0; i < 8; i++) {
        const float* rr = red + (ty8 + i) * 16;
        float rs = 0.f;
#pragma unroll
        for (int t = 0; t < 16; t++) rs += rr[t];
        l[i] = rs;
    }
    // store UNNORMALIZED exp into probsS
#pragma unroll
    for (int i = 0; i < 8; i++)
#pragma unroll
        for (int jj = 0; jj < 8; jj++)
            probsS[(ty8 + i) * 129 + tx8 + jj] = acc[i][jj];

    if (tx == 0) {
#pragma unroll
        for (int i = 0; i < 8; i++) {
            int row = ty8 + i;
            d_pm[((size_t)bh * KC + kc) * Gc + row] = m[i];
            d_pl[((size_t)bh * KC + kc) * Gc + row] = l[i];
        }
    }
    __syncthreads();

    // partial ctx accumulation: pacc = exp @ v_chunk
    {
        int r2 = tid >> 1, dg = tid & 1;
        float4 a4[8];
#pragma unroll
        for (int t = 0; t < 8; t++) a4[t] = make_float4(0.f, 0.f, 0.f, 0.f);
#pragma unroll 4
        for (int j = 0; j < 128; j++) {
            float p = probsS[r2 * 129 + j];
            const float4* g4 = (const float4*)(gvs + j * 64 + dg * 32);
#pragma unroll
            for (int t = 0; t < 8; t++) {
                float4 g = g4[t];
                a4[t].x = fmaf(p, g.x, a4[t].x);
                a4[t].y = fmaf(p, g.y, a4[t].y);
                a4[t].z = fmaf(p, g.z, a4[t].z);
                a4[t].w = fmaf(p, g.w, a4[t].w);
            }
        }
        float* pr = d_pacc + (((size_t)bh * KC + kc) * Gc + r2) * Dc + dg * 32;
#pragma unroll
        for (int t = 0; t < 8; t++) ((float4*)pr)[t] = a4[t];
    }
}

// ---------------------------------------------------------------------------
// Kernel D: combine the KC split-KV partials, overwrite global-query ctx rows
// Grid: (B*H), 256 threads (1 row handled by 2 threads of 32 d each)
// ---------------------------------------------------------------------------
__global__ void combine_kernel(float* __restrict__ ctx) {
    int bh = blockIdx.x;
    int b = bh / Hc;
    int c = d_gcnt[b];
    int tid = threadIdx.x;
    int r = tid >> 1, dg = tid & 1;
    if (r >= c) return;

    float mv[KC];
    float M = NEG_INF;
#pragma unroll
    for (int kc = 0; kc < KC; kc++) {
        mv[kc] = d_pm[((size_t)bh * KC + kc) * Gc + r];
        M = fmaxf(M, mv[kc]);
    }
    float L = 0.f;
    float4 s[8];
#pragma unroll
    for (int t = 0; t < 8; t++) s[t] = make_float4(0.f, 0.f, 0.f, 0.f);
#pragma unroll
    for (int kc = 0; kc < KC; kc++) {
        float wgt = __expf(mv[kc] - M);
        L = fmaf(d_pl[((size_t)bh * KC + kc) * Gc + r], wgt, L);
        const float4* pa = (const float4*)(d_pacc +
            (((size_t)bh * KC + kc) * Gc + r) * Dc + dg * 32);
#pragma unroll
        for (int t = 0; t < 8; t++) {
            float4 g = pa[t];
            s[t].x = fmaf(wgt, g.x, s[t].x);
            s[t].y = fmaf(wgt, g.y, s[t].y);
            s[t].z = fmaf(wgt, g.z, s[t].z);
            s[t].w = fmaf(wgt, g.w, s[t].w);
        }
    }
    float inv = 1.0f / L;
    int gi = d_gidx[b * Gc + r];
    float* crow = ctx + ((size_t)bh * Sc + gi) * Dc + dg * 32;
#pragma unroll
    for (int t = 0; t < 8; t++)
        ((float4*)crow)[t] = make_float4(s[t].x * inv, s[t].y * inv,
                                         s[t].z * inv, s[t].w * inv);
}

// ---------------------------------------------------------------------------
extern "C" void kernel_launch(void* const* d_in, const int* in_sizes, int n_in,
                              void* d_out, int out_size) {
    const float* q = (const float*)d_in[0];
    const float* k = (const float*)d_in[1];
    const float* v = (const float*)d_in[2];
    const int* mask = (const int*)d_in[3];

    float* ctx = (float*)d_out;
    float* probs = ctx + CTX_ELEMS;

    cudaFuncSetAttribute(global_attn_kernel,
                         cudaFuncAttributeMaxDynamicSharedMemorySize, SMEM_BYTES);
    cudaFuncSetAttribute(global_query_full_kernel,
                         cudaFuncAttributeMaxDynamicSharedMemorySize, SMEM_BYTES);

    build_index_kernel<<<Bc, 256>>>(mask);
    global_attn_kernel<<<dim3(Sc / QT, Hc, Bc), 256, SMEM_BYTES>>>(q, k, v, ctx, probs);
    global_query_full_kernel<<<dim3(KC, Hc, Bc), 256, SMEM_BYTES>>>(q, k, v);
    combine_kernel<<<Bc * Hc, 256>>>(ctx);
}

// round 2
// speedup vs baseline: 1.1305x; 1.1305x over previous
#include <cuda_runtime.h>

// Problem constants (fixed-shape problem)
constexpr int Bc = 2, Hc = 12, Sc = 2048, Dc = 64, Gc = 128;
constexpr int KC = 16;          // key chunks for the global-query full-attention pass
constexpr int QT = 128;         // query tile
constexpr long CTX_ELEMS = (long)Bc * Hc * Sc * Dc;

// Scratch (static __device__ arrays: allocation-free)
__device__ int   d_gidx[Bc * Gc];
__device__ int   d_gcnt[Bc];
__device__ float d_pacc[(size_t)Bc * Hc * KC * Gc * Dc];
__device__ float d_pm[Bc * Hc * KC * Gc];
__device__ float d_pl[Bc * Hc * KC * Gc];

// Shared memory layout (floats):
//   phase 1: qsT [64][128] at 0, ksT [64][128] at 8192
//   phase 2: probsS [128][129] at 0 (overlays qsT/ksT)
//   gvs [128][64] at 16512, red [128][16] at 24704
constexpr int SM_FLOATS = 16512 + 8192 + 2048;
constexpr int SMEM_BYTES = SM_FLOATS * 4;   // 107008 B -> 2 CTAs/SM

#define NEG_INF __int_as_float(0xff800000)

typedef unsigned long long ull;
__device__ __forceinline__ ull pack2(float x, float y) {
    ull r; asm("mov.b64 %0, {%1, %2};" : "=l"(r) : "f"(x), "f"(y)); return r;
}
__device__ __forceinline__ ull fma2(ull a, ull b, ull c) {
    ull d; asm("fma.rn.f32x2 %0, %1, %2, %3;" : "=l"(d) : "l"(a), "l"(b), "l"(c));
    return d;
}
__device__ __forceinline__ float2 unpack2(ull a) {
    float2 f; asm("mov.b64 {%0, %1}, %2;" : "=f"(f.x), "=f"(f.y) : "l"(a));
    return f;
}

// ---------------------------------------------------------------------------
// Kernel A: stable-order global index list per batch
// ---------------------------------------------------------------------------
__global__ void build_index_kernel(const int* __restrict__ mask) {
    int b = blockIdx.x;
    __shared__ int cnt[256];
    __shared__ int off[256];
    int tid = threadIdx.x;
    const int SEG = Sc / 256;
    int base = tid * SEG;
    int c = 0;
#pragma unroll
    for (int i = 0; i < SEG; i++) c += (mask[b * Sc + base + i] > 0);
    cnt[tid] = c;
    __syncthreads();
    if (tid == 0) {
        int s = 0;
        for (int t = 0; t < 256; t++) { off[t] = s; s += cnt[t]; }
        d_gcnt[b] = (s < Gc) ? s : Gc;
    }
    __syncthreads();
    int o = off[tid];
#pragma unroll
    for (int i = 0; i < SEG; i++) {
        if (mask[b * Sc + base + i] > 0) {
            if (o < Gc) d_gidx[b * Gc + o] = base + i;
            o++;
        }
    }
}

// ---------------------------------------------------------------------------
// Fused kernel: blockIdx.x in [0,16)  -> role B (global-branch attn + probs
//                                        output for a 128-query tile)
//               blockIdx.x in [16,32) -> role C (split-KV chunk kc = x-16 of
//                                        full attention for global queries)
// Grid: (32, H, B), 256 threads.
// ---------------------------------------------------------------------------
__global__ void __launch_bounds__(256, 2) fused_attn_kernel(
    const float* __restrict__ q, const float* __restrict__ k,
    const float* __restrict__ v, float* __restrict__ ctx,
    float* __restrict__ probs) {
    extern __shared__ float sm[];
    float* qsT    = sm;            // [64][128]
    float* ksT    = sm + 8192;     // [64][128]
    float* probsS = sm;            // [128][129] (overlays qsT/ksT after GEMM1)
    float* gvs    = sm + 16512;    // [128][64]
    float* red    = sm + 24704;    // [128][16]

    int tid = threadIdx.x;
    int h = blockIdx.y, b = blockIdx.z;
    int bh = b * Hc + h;
    int c = d_gcnt[b];
    bool roleB = blockIdx.x < 16;
    int q0 = roleB ? blockIdx.x * QT : 0;      // query tile origin (role B)
    int kc = roleB ? 0 : blockIdx.x - 16;      // key chunk (role C)
    int k0 = kc * 128;

    const float* qb = q + (size_t)bh * Sc * Dc;
    const float* kb = k + (size_t)bh * Sc * Dc;
    const float* vb = v + (size_t)bh * Sc * Dc;

    // ---- Load phase (transposed q & k tiles, plain v tile)
    {
        int r = tid & 127, half = tid >> 7;
        int d0base = half * 32;

        // Q rows: role B = tile rows; role C = gathered global queries
        bool qvalid = roleB || (r < c);
        int qrowi = roleB ? (q0 + r) : (qvalid ? d_gidx[b * Gc + r] : 0);
        const float* qrow = qb + (size_t)qrowi * Dc;
#pragma unroll
        for (int d0 = 0; d0 < 32; d0 += 4) {
            int dd = d0base + d0;
            float4 t = qvalid ? *(const float4*)(qrow + dd)
                              : make_float4(0.f, 0.f, 0.f, 0.f);
            qsT[(dd + 0) * 128 + r] = t.x;
            qsT[(dd + 1) * 128 + r] = t.y;
            qsT[(dd + 2) * 128 + r] = t.z;
            qsT[(dd + 3) * 128 + r] = t.w;
        }

        // K/V rows: role B = gathered global keys; role C = chunk rows
        bool kvalid = roleB ? (r < c) : true;
        int krowi = roleB ? (kvalid ? d_gidx[b * Gc + r] : 0) : (k0 + r);
        const float* krow = kb + (size_t)krowi * Dc;
        const float* vrow = vb + (size_t)krowi * Dc;
#pragma unroll
        for (int d0 = 0; d0 < 32; d0 += 4) {
            int dd = d0base + d0;
            float4 t = kvalid ? *(const float4*)(krow + dd)
                              : make_float4(0.f, 0.f, 0.f, 0.f);
            ksT[(dd + 0) * 128 + r] = t.x;
            ksT[(dd + 1) * 128 + r] = t.y;
            ksT[(dd + 2) * 128 + r] = t.z;
            ksT[(dd + 3) * 128 + r] = t.w;
            *(float4*)(gvs + r * 64 + dd) = kvalid ? *(const float4*)(vrow + dd)
                                                   : make_float4(0.f, 0.f, 0.f, 0.f);
        }
    }
    __syncthreads();

    // ---- GEMM1: scores[128q][128k], 8x8 per thread via packed f32x2 FMA.
    // Accumulators pair along the key (j) axis: B-operand pairs are
    // contiguous in ksT -> loaded directly as 64-bit; A is broadcast-packed.
    int lane = tid & 31, w = tid >> 5;
    int tx = ((w & 1) << 3) + (lane & 7);
    int ty = ((w >> 1) << 2) + (lane >> 3);
    int tx8 = tx * 8, ty8 = ty * 8;

    ull acc2[8][4];
#pragma unroll
    for (int i = 0; i < 8; i++)
#pragma unroll
        for (int jp = 0; jp < 4; jp++) acc2[i][jp] = 0ull;

#pragma unroll 4
    for (int d = 0; d < 64; d++) {
        float a[8];
        *(float4*)(a)     = *(const float4*)(qsT + d * 128 + ty8);
        *(float4*)(a + 4) = *(const float4*)(qsT + d * 128 + ty8 + 4);
        ull ap[8];
#pragma unroll
        for (int i = 0; i < 8; i++) ap[i] = pack2(a[i], a[i]);
        ull b2[4];
        const ull* bp = (const ull*)(ksT + d * 128 + tx8);
        b2[0] = bp[0]; b2[1] = bp[1]; b2[2] = bp[2]; b2[3] = bp[3];
#pragma unroll
        for (int i = 0; i < 8; i++)
#pragma unroll
            for (int jp = 0; jp < 4; jp++)
                acc2[i][jp] = fma2(ap[i], b2[jp], acc2[i][jp]);
    }

    // unpack, scale, mask
    float acc[8][8];
#pragma unroll
    for (int i = 0; i < 8; i++)
#pragma unroll
        for (int jp = 0; jp < 4; jp++) {
            float2 f = unpack2(acc2[i][jp]);
            acc[i][2 * jp]     = f.x;
            acc[i][2 * jp + 1] = f.y;
        }
#pragma unroll
    for (int jj = 0; jj < 8; jj++) {
        bool inval = roleB && ((tx8 + jj) >= c);
#pragma unroll
        for (int i = 0; i < 8; i++)
            acc[i][jj] = inval ? NEG_INF : acc[i][jj] * 0.125f;
    }

    // ---- softmax row stats (m, l) via smem reduction
    float m[8], l[8];
#pragma unroll
    for (int i = 0; i < 8; i++) {
        float rm = acc[i][0];
#pragma unroll
        for (int jj = 1; jj < 8; jj++) rm = fmaxf(rm, acc[i][jj]);
        red[(ty8 + i) * 16 + tx] = rm;
    }
    __syncthreads();
#pragma unroll
    for (int i = 0; i < 8; i++) {
        const float* rr = red + (ty8 + i) * 16;
        float rm = rr[0];
#pragma unroll
        for (int t = 1; t < 16; t++) rm = fmaxf(rm, rr[t]);
        m[i] = rm;
    }
    __syncthreads();
#pragma unroll
    for (int i = 0; i < 8; i++) {
        float rs = 0.f;
#pragma unroll
        for (int jj = 0; jj < 8; jj++) {
            float e = __expf(acc[i][jj] - m[i]);
            acc[i][jj] = e;
            rs += e;
        }
        red[(ty8 + i) * 16 + tx] = rs;
    }
    __syncthreads();
#pragma unroll
    for (int i = 0; i < 8; i++) {
        const float* rr = red + (ty8 + i) * 16;
        float rs = 0.f;
#pragma unroll
        for (int t = 0; t < 16; t++) rs += rr[t];
        l[i] = rs;
    }

    // probsS: role B = normalized probs; role C = unnormalized exp
#pragma unroll
    for (int i = 0; i < 8; i++) {
        float norm = roleB ? (1.0f / l[i]) : 1.0f;
#pragma unroll
        for (int jj = 0; jj < 8; jj++)
            probsS[(ty8 + i) * 129 + tx8 + jj] = acc[i][jj] * norm;
    }
    if (!roleB && tx == 0) {
#pragma unroll
        for (int i = 0; i < 8; i++) {
            int row = ty8 + i;
            d_pm[((size_t)bh * KC + kc) * Gc + row] = m[i];
            d_pl[((size_t)bh * KC + kc) * Gc + row] = l[i];
        }
    }
    __syncthreads();

    if (roleB) {
        // ---- probs gmem write: 128 computed cols + 1920 zeros, streaming
        float* prow = probs + ((size_t)bh * Sc + q0) * Sc;
        for (int i2 = tid; i2 < 128 * 512; i2 += 256) {
            int rr = i2 >> 9, c4 = i2 & 511;   // warp-uniform branch (aligned at 32)
            float4 val = make_float4(0.f, 0.f, 0.f, 0.f);
            if (c4 < 32) {
                const float* p = probsS + rr * 129 + c4 * 4;
                val = make_float4(p[0], p[1], p[2], p[3]);
            }
            __stcs((float4*)(prow + (size_t)rr * Sc + (c4 << 2)), val);
        }
    }

    // ---- GEMM2: out[128][64] = probsS @ gvs, packed f32x2.
    {
        int r2 = tid >> 1, dg = tid & 1;
        ull a2[16];
#pragma unroll
        for (int t = 0; t < 16; t++) a2[t] = 0ull;
#pragma unroll 4
        for (int j = 0; j < 128; j++) {
            float p = probsS[r2 * 129 + j];
            ull pp = pack2(p, p);
            const ull* g2 = (const ull*)(gvs + j * 64 + dg * 32);
#pragma unroll
            for (int t = 0; t < 16; t++) a2[t] = fma2(pp, g2[t], a2[t]);
        }
        float* orow = roleB
            ? (ctx + ((size_t)bh * Sc + q0 + r2) * Dc + dg * 32)
            : (d_pacc + (((size_t)bh * KC + kc) * Gc + r2) * Dc + dg * 32);
        ull* o2 = (ull*)orow;
#pragma unroll
        for (int t = 0; t < 16; t++) o2[t] = a2[t];
    }
}

// ---------------------------------------------------------------------------
// Combine: merge KC split-KV partials, overwrite global-query ctx rows.
// Grid: (B*H, 8), 256 threads. Block = 16 rows; thread = (row, float4 seg).
// ---------------------------------------------------------------------------
__global__ void combine_kernel(float* __restrict__ ctx) {
    int bh = blockIdx.x;
    int b = bh / Hc;
    int c = d_gcnt[b];
    int tid = threadIdx.x;
    int rl = tid >> 4, seg = tid & 15;
    int r = blockIdx.y * 16 + rl;
    if (r >= c) return;

    float mv[KC];
    float M = NEG_INF;
#pragma unroll
    for (int kc = 0; kc < KC; kc++) {
        mv[kc] = d_pm[((size_t)bh * KC + kc) * Gc + r];
        M = fmaxf(M, mv[kc]);
    }
    float L = 0.f;
    float4 s = make_float4(0.f, 0.f, 0.f, 0.f);
#pragma unroll
    for (int kc = 0; kc < KC; kc++) {
        float wgt = __expf(mv[kc] - M);
        L = fmaf(d_pl[((size_t)bh * KC + kc) * Gc + r], wgt, L);
        float4 g = *(const float4*)(d_pacc +
            (((size_t)bh * KC + kc) * Gc + r) * (size_t)Dc + seg * 4);
        s.x = fmaf(wgt, g.x, s.x);
        s.y = fmaf(wgt, g.y, s.y);
        s.z = fmaf(wgt, g.z, s.z);
        s.w = fmaf(wgt, g.w, s.w);
    }
    float inv = 1.0f / L;
    int gi = d_gidx[b * Gc + r];
    *(float4*)(ctx + ((size_t)bh * Sc + gi) * Dc + seg * 4) =
        make_float4(s.x * inv, s.y * inv, s.z * inv, s.w * inv);
}

// ---------------------------------------------------------------------------
extern "C" void kernel_launch(void* const* d_in, const int* in_sizes, int n_in,
                              void* d_out, int out_size) {
    const float* q = (const float*)d_in[0];
    const float* k = (const float*)d_in[1];
    const float* v = (const float*)d_in[2];
    const int* mask = (const int*)d_in[3];

    float* ctx = (float*)d_out;
    float* probs = ctx + CTX_ELEMS;

    cudaFuncSetAttribute(fused_attn_kernel,
                         cudaFuncAttributeMaxDynamicSharedMemorySize, SMEM_BYTES);

    build_index_kernel<<<Bc, 256>>>(mask);
    fused_attn_kernel<<<dim3(32, Hc, Bc), 256, SMEM_BYTES>>>(q, k, v, ctx, probs);
    combine_kernel<<<dim3(Bc * Hc, 8), 256>>>(ctx);
}

// round 3
// speedup vs baseline: 1.1519x; 1.0189x over previous
#include <cuda_runtime.h>

// Problem constants (fixed-shape problem)
constexpr int Bc = 2, Hc = 12, Sc = 2048, Dc = 64, Gc = 128;
constexpr int KC = 16;          // key chunks for the global-query full pass
constexpr int QT = 128;
constexpr long CTX_ELEMS = (long)Bc * Hc * Sc * Dc;

// Scratch (static __device__ arrays: allocation-free)
__device__ int   d_gidx[Bc * Gc];
__device__ int   d_gcnt[Bc];
__device__ float d_pacc[(size_t)Bc * Hc * KC * Gc * Dc];
__device__ float d_pm[Bc * Hc * KC * Gc];
__device__ float d_pl[Bc * Hc * KC * Gc];

// Shared memory layout (floats):
//   qsT [64][128] @0, ksT [64][128] @8192  (probsS [128][129] overlays @0)
//   gvs [128][64] @16512, red [128][16] @24704, linv[128] @26752
constexpr int SM_FLOATS = 16512 + 8192 + 2048 + 128;   // 26880
constexpr int SMEM_BYTES = SM_FLOATS * 4;              // 107520 B -> 2 CTAs/SM

#define NEG_INF __int_as_float(0xff800000)

typedef unsigned long long ull;
__device__ __forceinline__ ull pack2(float x, float y) {
    ull r; asm("mov.b64 %0, {%1, %2};" : "=l"(r) : "f"(x), "f"(y)); return r;
}
__device__ __forceinline__ ull fma2(ull a, ull b, ull c) {
    ull d; asm("fma.rn.f32x2 %0, %1, %2, %3;" : "=l"(d) : "l"(a), "l"(b), "l"(c));
    return d;
}
__device__ __forceinline__ float2 unpack2(ull a) {
    float2 f; asm("mov.b64 {%0, %1}, %2;" : "=f"(f.x), "=f"(f.y) : "l"(a));
    return f;
}

// ---------------------------------------------------------------------------
// Kernel A: stable-order global index list per batch (warp-scan, no serial)
// ---------------------------------------------------------------------------
__global__ void build_index_kernel(const int* __restrict__ mask) {
    int b = blockIdx.x;
    __shared__ int wtot[8];
    int tid = threadIdx.x, lane = tid & 31, w = tid >> 5;
    const int SEG = Sc / 256;  // 8
    int base = tid * SEG;
    int mv[SEG];
    int c = 0;
#pragma unroll
    for (int i = 0; i < SEG; i++) { mv[i] = mask[b * Sc + base + i] > 0; c += mv[i]; }
    // inclusive warp scan of c
    int sc = c;
#pragma unroll
    for (int d = 1; d < 32; d <<= 1) {
        int t = __shfl_up_sync(0xffffffffu, sc, d);
        if (lane >= d) sc += t;
    }
    if (lane == 31) wtot[w] = sc;
    __syncthreads();
    int woff = 0;
#pragma unroll
    for (int t = 0; t < 8; t++) woff += (t < w) ? wtot[t] : 0;
    if (tid == 0) {
        int s = 0;
#pragma unroll
        for (int t = 0; t < 8; t++) s += wtot[t];
        d_gcnt[b] = (s < Gc) ? s : Gc;
    }
    int o = woff + sc - c;  // exclusive prefix for this thread
#pragma unroll
    for (int i = 0; i < SEG; i++) {
        if (mv[i]) {
            if (o < Gc) d_gidx[b * Gc + o] = base + i;
            o++;
        }
    }
}

// ---------------------------------------------------------------------------
// Fused kernel. Grid (48, H, B), 256 threads.
//   x in [0,16)  -> fill: zero probs cols [128,2048) for 128 rows
//   x in [16,32) -> roleB: global-branch attn + probs cols [0,128) + ctx
//   x in [32,48) -> roleC: split-KV chunk of full attn for global queries
// ---------------------------------------------------------------------------
__global__ void __launch_bounds__(256, 2) fused_attn_kernel(
    const float* __restrict__ q, const float* __restrict__ k,
    const float* __restrict__ v, float* __restrict__ ctx,
    float* __restrict__ probs) {
    extern __shared__ float sm[];
    float* qsT    = sm;            // [64][128]
    float* ksT    = sm + 8192;     // [64][128]
    float* probsS = sm;            // [128][129] overlays qsT/ksT after GEMM1
    float* gvs    = sm + 16512;    // [128][64]
    float* red    = sm + 24704;    // [128][16]
    float* linv   = sm + 26752;    // [128]

    int tid = threadIdx.x;
    int h = blockIdx.y, b = blockIdx.z;
    int bh = b * Hc + h;

    // ---------------- fill role: pure streaming zero store ----------------
    if (blockIdx.x < 16) {
        int fx = blockIdx.x;
        int lane = tid & 31, w = tid >> 5;
        float* base = probs + ((size_t)bh * Sc + fx * 128) * Sc + 128;
        float4 z = make_float4(0.f, 0.f, 0.f, 0.f);
        for (int r = w; r < 128; r += 8) {
            float4* p = (float4*)(base + (size_t)r * Sc);
#pragma unroll 5
            for (int cc = lane; cc < 480; cc += 32) __stcs(p + cc, z);
        }
        return;
    }

    bool roleB = blockIdx.x < 32;
    int q0 = roleB ? (blockIdx.x - 16) * QT : 0;
    int kc = roleB ? 0 : blockIdx.x - 32;
    int k0 = kc * 128;
    int c = d_gcnt[b];

    const float* qb = q + (size_t)bh * Sc * Dc;
    const float* kb = k + (size_t)bh * Sc * Dc;
    const float* vb = v + (size_t)bh * Sc * Dc;

    // ---- Load phase (transposed q & k tiles, plain v tile)
    {
        int r = tid & 127, half = tid >> 7;
        int d0base = half * 32;

        bool qvalid = roleB || (r < c);
        int qrowi = roleB ? (q0 + r) : (qvalid ? d_gidx[b * Gc + r] : 0);
        const float* qrow = qb + (size_t)qrowi * Dc;
#pragma unroll
        for (int d0 = 0; d0 < 32; d0 += 4) {
            int dd = d0base + d0;
            float4 t = qvalid ? *(const float4*)(qrow + dd)
                              : make_float4(0.f, 0.f, 0.f, 0.f);
            qsT[(dd + 0) * 128 + r] = t.x;
            qsT[(dd + 1) * 128 + r] = t.y;
            qsT[(dd + 2) * 128 + r] = t.z;
            qsT[(dd + 3) * 128 + r] = t.w;
        }

        bool kvalid = roleB ? (r < c) : true;
        int krowi = roleB ? (kvalid ? d_gidx[b * Gc + r] : 0) : (k0 + r);
        const float* krow = kb + (size_t)krowi * Dc;
        const float* vrow = vb + (size_t)krowi * Dc;
#pragma unroll
        for (int d0 = 0; d0 < 32; d0 += 4) {
            int dd = d0base + d0;
            float4 t = kvalid ? *(const float4*)(krow + dd)
                              : make_float4(0.f, 0.f, 0.f, 0.f);
            ksT[(dd + 0) * 128 + r] = t.x;
            ksT[(dd + 1) * 128 + r] = t.y;
            ksT[(dd + 2) * 128 + r] = t.z;
            ksT[(dd + 3) * 128 + r] = t.w;
            *(float4*)(gvs + r * 64 + dd) = kvalid ? *(const float4*)(vrow + dd)
                                                   : make_float4(0.f, 0.f, 0.f, 0.f);
        }
    }
    __syncthreads();

    // ---- GEMM1: scores[128q][128k], 8x8/thread, packed f32x2 accumulators.
    int lane = tid & 31, w = tid >> 5;
    int tx = ((w & 1) << 3) + (lane & 7);
    int ty = ((w >> 1) << 2) + (lane >> 3);
    int tx8 = tx * 8, ty8 = ty * 8;

    ull acc2[8][4];
#pragma unroll
    for (int i = 0; i < 8; i++)
#pragma unroll
        for (int jp = 0; jp < 4; jp++) acc2[i][jp] = 0ull;

#pragma unroll 8
    for (int d = 0; d < 64; d++) {
        float4 a0 = *(const float4*)(qsT + d * 128 + ty8);
        float4 a1 = *(const float4*)(qsT + d * 128 + ty8 + 4);
        ull ap[8];
        ap[0] = pack2(a0.x, a0.x); ap[1] = pack2(a0.y, a0.y);
        ap[2] = pack2(a0.z, a0.z); ap[3] = pack2(a0.w, a0.w);
        ap[4] = pack2(a1.x, a1.x); ap[5] = pack2(a1.y, a1.y);
        ap[6] = pack2(a1.z, a1.z); ap[7] = pack2(a1.w, a1.w);
        const ull* bp = (const ull*)(ksT + d * 128 + tx8);
        ull b0 = bp[0], b1 = bp[1], b2 = bp[2], b3 = bp[3];
#pragma unroll
        for (int i = 0; i < 8; i++) {
            acc2[i][0] = fma2(ap[i], b0, acc2[i][0]);
            acc2[i][1] = fma2(ap[i], b1, acc2[i][1]);
            acc2[i][2] = fma2(ap[i], b2, acc2[i][2]);
            acc2[i][3] = fma2(ap[i], b3, acc2[i][3]);
        }
    }

    // ---- softmax pass 1: per-row max (unpack on the fly, low reg pressure)
#pragma unroll
    for (int i = 0; i < 8; i++) {
        float rm = NEG_INF;
#pragma unroll
        for (int jp = 0; jp < 4; jp++) {
            float2 f = unpack2(acc2[i][jp]);
            bool iv0 = roleB && ((tx8 + 2 * jp)     >= c);
            bool iv1 = roleB && ((tx8 + 2 * jp + 1) >= c);
            float s0 = iv0 ? NEG_INF : f.x * 0.125f;
            float s1 = iv1 ? NEG_INF : f.y * 0.125f;
            rm = fmaxf(rm, fmaxf(s0, s1));
        }
        red[(ty8 + i) * 16 + tx] = rm;
    }
    __syncthreads();
    float m[8];
#pragma unroll
    for (int i = 0; i < 8; i++) {
        const float* rr = red + (ty8 + i) * 16;
        float rm = rr[0];
#pragma unroll
        for (int t = 1; t < 16; t++) rm = fmaxf(rm, rr[t]);
        m[i] = rm;
    }
    __syncthreads();

    // ---- softmax pass 2: exp -> probsS (UNNORMALIZED), partial sums -> red
#pragma unroll
    for (int i = 0; i < 8; i++) {
        float rs = 0.f;
        float* pr = probsS + (ty8 + i) * 129 + tx8;
#pragma unroll
        for (int jp = 0; jp < 4; jp++) {
            float2 f = unpack2(acc2[i][jp]);
            bool iv0 = roleB && ((tx8 + 2 * jp)     >= c);
            bool iv1 = roleB && ((tx8 + 2 * jp + 1) >= c);
            float e0 = iv0 ? 0.f : __expf(f.x * 0.125f - m[i]);
            float e1 = iv1 ? 0.f : __expf(f.y * 0.125f - m[i]);
            pr[2 * jp]     = e0;
            pr[2 * jp + 1] = e1;
            rs += e0 + e1;
        }
        red[(ty8 + i) * 16 + tx] = rs;
    }
    __syncthreads();
#pragma unroll
    for (int i = 0; i < 8; i++) {
        const float* rr = red + (ty8 + i) * 16;
        float rs = 0.f;
#pragma unroll
        for (int t = 0; t < 16; t++) rs += rr[t];
        if (tx == 0) {
            int row = ty8 + i;
            linv[row] = 1.0f / rs;
            if (!roleB) {
                d_pm[((size_t)bh * KC + kc) * Gc + row] = m[i];
                d_pl[((size_t)bh * KC + kc) * Gc + row] = rs;
            }
        }
    }
    __syncthreads();

    if (roleB) {
        // ---- probs computed cols [0,128): normalized, streaming stores
        float* prow = probs + ((size_t)bh * Sc + q0) * Sc;
        for (int i2 = tid; i2 < 128 * 32; i2 += 256) {
            int rr = i2 >> 5, c4 = i2 & 31;
            float inv = linv[rr];
            const float* p = probsS + rr * 129 + c4 * 4;
            __stcs((float4*)(prow + (size_t)rr * Sc + (c4 << 2)),
                   make_float4(p[0] * inv, p[1] * inv, p[2] * inv, p[3] * inv));
        }
    }

    // ---- GEMM2: out[128][64] = probsS @ gvs (packed f32x2), scale at end
    {
        int r2 = tid >> 1, dg = tid & 1;
        ull a2[16];
#pragma unroll
        for (int t = 0; t < 16; t++) a2[t] = 0ull;
#pragma unroll 8
        for (int j = 0; j < 128; j++) {
            float p = probsS[r2 * 129 + j];
            ull pp = pack2(p, p);
            const ull* g2 = (const ull*)(gvs + j * 64 + dg * 32);
#pragma unroll
            for (int t = 0; t < 16; t++) a2[t] = fma2(pp, g2[t], a2[t]);
        }
        if (roleB) {
            float inv = linv[r2];
            float* orow = ctx + ((size_t)bh * Sc + q0 + r2) * Dc + dg * 32;
#pragma unroll
            for (int t = 0; t < 16; t++) {
                float2 f = unpack2(a2[t]);
                ((float2*)orow)[t] = make_float2(f.x * inv, f.y * inv);
            }
        } else {
            ull* o2 = (ull*)(d_pacc + (((size_t)bh * KC + kc) * Gc + r2) * Dc + dg * 32);
#pragma unroll
            for (int t = 0; t < 16; t++) o2[t] = a2[t];
        }
    }
}

// ---------------------------------------------------------------------------
// Combine: merge KC split-KV partials, overwrite global-query ctx rows.
// Grid: (B*H, 8), 256 threads.
// ---------------------------------------------------------------------------
__global__ void combine_kernel(float* __restrict__ ctx) {
    int bh = blockIdx.x;
    int b = bh / Hc;
    int c = d_gcnt[b];
    int tid = threadIdx.x;
    int rl = tid >> 4, seg = tid & 15;
    int r = blockIdx.y * 16 + rl;
    if (r >= c) return;

    float mv[KC];
    float M = NEG_INF;
#pragma unroll
    for (int kc = 0; kc < KC; kc++) {
        mv[kc] = d_pm[((size_t)bh * KC + kc) * Gc + r];
        M = fmaxf(M, mv[kc]);
    }
    float L = 0.f;
    float4 s = make_float4(0.f, 0.f, 0.f, 0.f);
#pragma unroll
    for (int kc = 0; kc < KC; kc++) {
        float wgt = __expf(mv[kc] - M);
        L = fmaf(d_pl[((size_t)bh * KC + kc) * Gc + r], wgt, L);
        float4 g = *(const float4*)(d_pacc +
            (((size_t)bh * KC + kc) * Gc + r) * (size_t)Dc + seg * 4);
        s.x = fmaf(wgt, g.x, s.x);
        s.y = fmaf(wgt, g.y, s.y);
        s.z = fmaf(wgt, g.z, s.z);
        s.w = fmaf(wgt, g.w, s.w);
    }
    float inv = 1.0f / L;
    int gi = d_gidx[b * Gc + r];
    *(float4*)(ctx + ((size_t)bh * Sc + gi) * Dc + seg * 4) =
        make_float4(s.x * inv, s.y * inv, s.z * inv, s.w * inv);
}

// Trailing no-op so the 6th launch of the run (ncu -s 5 -c 1 window) is the
// fused kernel: per call = [build, fused, combine, dummy] -> launch #6 = fused.
__global__ void dummy_kernel() {}

// ---------------------------------------------------------------------------
extern "C" void kernel_launch(void* const* d_in, const int* in_sizes, int n_in,
                              void* d_out, int out_size) {
    const float* q = (const float*)d_in[0];
    const float* k = (const float*)d_in[1];
    const float* v = (const float*)d_in[2];
    const int* mask = (const int*)d_in[3];

    float* ctx = (float*)d_out;
    float* probs = ctx + CTX_ELEMS;

    cudaFuncSetAttribute(fused_attn_kernel,
                         cudaFuncAttributeMaxDynamicSharedMemorySize, SMEM_BYTES);

    build_index_kernel<<<Bc, 256>>>(mask);
    fused_attn_kernel<<<dim3(48, Hc, Bc), 256, SMEM_BYTES>>>(q, k, v, ctx, probs);
    combine_kernel<<<dim3(Bc * Hc, 8), 256>>>(ctx);
    dummy_kernel<<<1, 32>>>();
}